// round 14
// baseline (speedup 1.0000x reference)
#include <cuda_runtime.h>
#include <cuda_bf16.h>
#include <cstdint>

#define N_NODES 50000
#define N_EDGES 800000
#define D 128
#define BN_EPS 1e-5f
#define SLOTS 64
#define OVF_MAX 8192

// ---------------- scratch (no allocation allowed) ----------------
__device__ float g_agg[N_NODES * D];
__device__ float g_h1[N_NODES * D];
__device__ float g_h2[N_NODES * D];
__device__ float g_sum1[D], g_sq1[D], g_sum2[D], g_sq2[D];
__device__ float g_scale[D];
__device__ float g_shift[D];
__device__ int   g_cnt[N_NODES];
__device__ uint2 g_slots[N_NODES * SLOTS];   // {col, val bits}
__device__ int   g_ovf_cnt;
__device__ int   g_ovf[OVF_MAX];
// transposed + bf16-split weights: wt[n*D+k] = W[k*D+n]
__device__ __nv_bfloat16 g_w1hi[D * D];
__device__ __nv_bfloat16 g_w1lo[D * D];
__device__ __nv_bfloat16 g_w2hi[D * D];
__device__ __nv_bfloat16 g_w2lo[D * D];

__device__ __forceinline__ float swishf(float h) {
    return h / (1.0f + __expf(-h));
}

__device__ __forceinline__ uint32_t pack2(float a, float b) {
    __nv_bfloat162 t = __floats2bfloat162_rn(a, b);
    return *reinterpret_cast<uint32_t*>(&t);
}

__device__ __forceinline__ uint32_t smem_u32(const void* p) {
    uint32_t a;
    asm("{ .reg .u64 t; cvta.to.shared.u64 t, %1; cvt.u32.u64 %0, t; }"
        : "=r"(a) : "l"(p));
    return a;
}

// ---------------- 0) prep: weight split + zero counters/stats ----------------
__global__ void prep_kernel(const float* __restrict__ W1,
                            const float* __restrict__ W2) {
    int i = blockIdx.x * blockDim.x + threadIdx.x;   // 196*256 = 50176 threads
    if (i < D * D) {
        int n = i >> 7, k = i & (D - 1);
        float v1 = W1[k * D + n];
        float h1 = __bfloat162float(__float2bfloat16(v1));
        g_w1hi[i] = __float2bfloat16(v1);
        g_w1lo[i] = __float2bfloat16(v1 - h1);
        float v2 = W2[k * D + n];
        float h2 = __bfloat162float(__float2bfloat16(v2));
        g_w2hi[i] = __float2bfloat16(v2);
        g_w2lo[i] = __float2bfloat16(v2 - h2);
    }
    if (i < N_NODES) g_cnt[i] = 0;
    if (i < D) { g_sum1[i] = 0.f; g_sq1[i] = 0.f; g_sum2[i] = 0.f; g_sq2[i] = 0.f; }
    if (i == 0) g_ovf_cnt = 0;
}

// ---------------- 1) scatter edges into per-row slots ----------------
__global__ void scatter_kernel(const float* __restrict__ vals,
                               const int* __restrict__ rows,
                               const int* __restrict__ cols) {
    int e = blockIdx.x * blockDim.x + threadIdx.x;
    if (e >= N_EDGES) return;
    int r = __ldg(rows + e);
    int pos = atomicAdd(g_cnt + r, 1);
    if (pos < SLOTS) {
        uint2 cv;
        cv.x = (uint32_t)__ldg(cols + e);
        cv.y = __float_as_uint(__ldg(vals + e));
        g_slots[r * SLOTS + pos] = cv;
    } else {
        int o = atomicAdd(&g_ovf_cnt, 1);
        if (o < OVF_MAX) g_ovf[o] = e;
    }
}

// ---------------- 2) gather: agg[r] = (1+eps)x[r] + sum_slots val*x[col] ----------------
__global__ void gather_kernel(const float* __restrict__ x,
                              const float* __restrict__ eps) {
    int r = blockIdx.x * 8 + (threadIdx.x >> 5);
    int lane = threadIdx.x & 31;
    if (r >= N_NODES) return;
    int lane4 = lane * 4;

    float s = 1.0f + __ldg(eps);
    float4 acc = __ldg((const float4*)(x + (size_t)r * D + lane4));
    acc.x *= s; acc.y *= s; acc.z *= s; acc.w *= s;

    int n = g_cnt[r];
    if (n > SLOTS) n = SLOTS;
    uint2 cv0 = make_uint2(0, 0), cv1 = make_uint2(0, 0);
    if (lane < n) cv0 = g_slots[r * SLOTS + lane];
    if (lane + 32 < n) cv1 = g_slots[r * SLOTS + lane + 32];

    for (int j = 0; j < n; j += 4) {
        float4 m[4];
        float vv[4];
#pragma unroll
        for (int u = 0; u < 4; u++) {
            int jj = j + u;
            if (jj < n) {   // uniform branch
                uint32_t cx = __shfl_sync(0xffffffffu, (jj < 32) ? cv0.x : cv1.x, jj & 31);
                uint32_t cy = __shfl_sync(0xffffffffu, (jj < 32) ? cv0.y : cv1.y, jj & 31);
                vv[u] = __uint_as_float(cy);
                m[u] = __ldg((const float4*)(x + (size_t)cx * D + lane4));
            } else {
                vv[u] = 0.f;
                m[u] = make_float4(0.f, 0.f, 0.f, 0.f);
            }
        }
#pragma unroll
        for (int u = 0; u < 4; u++) {
            acc.x = fmaf(vv[u], m[u].x, acc.x);
            acc.y = fmaf(vv[u], m[u].y, acc.y);
            acc.z = fmaf(vv[u], m[u].z, acc.z);
            acc.w = fmaf(vv[u], m[u].w, acc.w);
        }
    }
    *(float4*)(g_agg + (size_t)r * D + lane4) = acc;
}

// ---------------- 2b) fixup: overflow edges (rare path, usually empty) ----------------
__global__ void fixup_kernel(const float* __restrict__ x,
                             const float* __restrict__ vals,
                             const int* __restrict__ rows,
                             const int* __restrict__ cols) {
    int n = g_ovf_cnt;
    if (n > OVF_MAX) n = OVF_MAX;
    int wid = threadIdx.x >> 5;
    int lane = threadIdx.x & 31;
    for (int i = wid; i < n; i += 8) {
        int e = g_ovf[i];
        int r = rows[e], c = cols[e];
        float v = vals[e];
        float4 m = __ldg((const float4*)(x + (size_t)c * D) + lane);
        m.x *= v; m.y *= v; m.z *= v; m.w *= v;
        float* dst = g_agg + (size_t)r * D + lane * 4;
        asm volatile("red.global.add.v4.f32 [%0], {%1,%2,%3,%4};"
                     :: "l"(dst), "f"(m.x), "f"(m.y), "f"(m.z), "f"(m.w)
                     : "memory");
    }
}

// ---------------- 3) mma.sync GEMM, 16 warps (N split): C = f(A) @ W + b ----------------
#define LDT (D + 8)             // 136 bf16 per row
#define TILE_B (128 * LDT * 2)  // 34816 bytes per tile

__device__ __forceinline__ void mma16816(float* c, const uint32_t* a,
                                         uint32_t b0, uint32_t b1) {
    asm volatile(
        "mma.sync.aligned.m16n8k16.row.col.f32.bf16.bf16.f32 "
        "{%0,%1,%2,%3}, {%4,%5,%6,%7}, {%8,%9}, {%0,%1,%2,%3};"
        : "+f"(c[0]), "+f"(c[1]), "+f"(c[2]), "+f"(c[3])
        : "r"(a[0]), "r"(a[1]), "r"(a[2]), "r"(a[3]), "r"(b0), "r"(b1));
}

__device__ __forceinline__ void ldsm4(uint32_t* r, uint32_t addr) {
    asm volatile("ldmatrix.sync.aligned.m8n8.x4.shared.b16 {%0,%1,%2,%3}, [%4];"
                 : "=r"(r[0]), "=r"(r[1]), "=r"(r[2]), "=r"(r[3])
                 : "r"(addr));
}

template <bool PRE>
__global__ __launch_bounds__(512, 1) void gemm_mma_kernel(
    const float* __restrict__ A,
    const __nv_bfloat16* __restrict__ Whi,
    const __nv_bfloat16* __restrict__ Wlo,
    const float* __restrict__ bias,
    float* __restrict__ C) {
    extern __shared__ char smem[];
    __nv_bfloat16* sAhi = (__nv_bfloat16*)(smem);
    __nv_bfloat16* sAlo = (__nv_bfloat16*)(smem + TILE_B);
    __nv_bfloat16* sWhi = (__nv_bfloat16*)(smem + 2 * TILE_B);
    __nv_bfloat16* sWlo = (__nv_bfloat16*)(smem + 3 * TILE_B);
    __shared__ float sb[D], ssc[D], ssh[D];

    int tid = threadIdx.x;
    int wid = tid >> 5;
    int lane = tid & 31;
    int row0 = blockIdx.x * 128;

    if (tid < D) {
        sb[tid] = __ldg(bias + tid);
        if (PRE) { ssc[tid] = g_scale[tid]; ssh[tid] = g_shift[tid]; }
    }
    __syncthreads();   // ssc/ssh read cross-thread below (R7 race fix)

    // ---- fill W tiles: thread t -> row t/4, quarter (t&3)*32 ----
    {
        int n = tid >> 2;
        int c0 = (tid & 3) * 32;
        const __nv_bfloat16* wh = Whi + n * D + c0;
        const __nv_bfloat16* wl = Wlo + n * D + c0;
        __nv_bfloat16* dh = sWhi + n * LDT + c0;
        __nv_bfloat16* dl = sWlo + n * LDT + c0;
#pragma unroll
        for (int j = 0; j < 32; j += 8) {
            *(uint4*)(dh + j) = *(const uint4*)(wh + j);
            *(uint4*)(dl + j) = *(const uint4*)(wl + j);
        }
    }

    // ---- fill A tiles (fp32 load, optional BN+swish, hi/lo split) ----
    {
        int r = tid >> 2;
        int c0 = (tid & 3) * 32;
        int grow = row0 + r;
        bool valid = grow < N_NODES;
        const float* Ar = A + (size_t)grow * D + c0;
        __nv_bfloat16* dh = sAhi + r * LDT + c0;
        __nv_bfloat16* dl = sAlo + r * LDT + c0;
#pragma unroll
        for (int j = 0; j < 32; j += 8) {
            float f[8];
            if (valid) {
                float4 v0 = *(const float4*)(Ar + j);
                float4 v1 = *(const float4*)(Ar + j + 4);
                f[0] = v0.x; f[1] = v0.y; f[2] = v0.z; f[3] = v0.w;
                f[4] = v1.x; f[5] = v1.y; f[6] = v1.z; f[7] = v1.w;
                if (PRE) {
#pragma unroll
                    for (int q = 0; q < 8; q++)
                        f[q] = swishf(fmaf(f[q], ssc[c0 + j + q], ssh[c0 + j + q]));
                }
            } else {
#pragma unroll
                for (int q = 0; q < 8; q++) f[q] = 0.f;
            }
            uint4 hi, lo;
            float hf[8];
#pragma unroll
            for (int q = 0; q < 8; q++)
                hf[q] = __bfloat162float(__float2bfloat16(f[q]));
            hi.x = pack2(f[0], f[1]); hi.y = pack2(f[2], f[3]);
            hi.z = pack2(f[4], f[5]); hi.w = pack2(f[6], f[7]);
            lo.x = pack2(f[0] - hf[0], f[1] - hf[1]);
            lo.y = pack2(f[2] - hf[2], f[3] - hf[3]);
            lo.z = pack2(f[4] - hf[4], f[5] - hf[5]);
            lo.w = pack2(f[6] - hf[6], f[7] - hf[7]);
            *(uint4*)(dh + j) = hi;
            *(uint4*)(dl + j) = lo;
        }
    }
    __syncthreads();

    // ---- MMA mainloop: warp = (mg, nh); 16 rows x 64 cols per warp ----
    int mg = wid & 7;            // M group: rows mg*16..mg*16+15
    int nh = wid >> 3;           // N half: cols nh*64..nh*64+63
    int group = lane >> 2;
    int tig = lane & 3;
    int mrow = mg * 16;
    int ncol0 = nh * 64;

    int aRow = mrow + ((lane >> 3) & 1) * 8 + (lane & 7);
    int aKadd = (lane >> 4) * 8;
    uint32_t aHiBase = smem_u32(sAhi) + (uint32_t)(aRow * LDT + aKadd) * 2u;
    uint32_t aLoBase = smem_u32(sAlo) + (uint32_t)(aRow * LDT + aKadd) * 2u;
    int bRowOff = ncol0 + ((lane >> 4) << 3) + (lane & 7);
    int bKadd = ((lane >> 3) & 1) * 8;
    uint32_t bHiBase = smem_u32(sWhi) + (uint32_t)(bRowOff * LDT + bKadd) * 2u;
    uint32_t bLoBase = smem_u32(sWlo) + (uint32_t)(bRowOff * LDT + bKadd) * 2u;

    float acc[8][4];
#pragma unroll
    for (int t = 0; t < 8; t++)
#pragma unroll
        for (int j = 0; j < 4; j++) acc[t][j] = 0.f;

#pragma unroll
    for (int kt = 0; kt < 8; kt++) {
        uint32_t kb = (uint32_t)(kt * 16) * 2u;
        uint32_t ahi[4], alo[4];
        ldsm4(ahi, aHiBase + kb);
        ldsm4(alo, aLoBase + kb);
#pragma unroll
        for (int p = 0; p < 4; p++) {
            uint32_t poff = (uint32_t)(p * 16 * LDT) * 2u;
            uint32_t bh[4], bl[4];
            ldsm4(bh, bHiBase + poff + kb);
            ldsm4(bl, bLoBase + poff + kb);
            mma16816(acc[2 * p], ahi, bh[0], bh[1]);
            mma16816(acc[2 * p], alo, bh[0], bh[1]);
            mma16816(acc[2 * p], ahi, bl[0], bl[1]);
            mma16816(acc[2 * p + 1], ahi, bh[2], bh[3]);
            mma16816(acc[2 * p + 1], alo, bh[2], bh[3]);
            mma16816(acc[2 * p + 1], ahi, bl[2], bl[3]);
        }
    }

    // ---- epilogue: add bias, store fp32 ----
    {
        int r0 = row0 + mrow + group;
        int r1 = r0 + 8;
        bool v0 = r0 < N_NODES;
        bool v1 = r1 < N_NODES;
        float* C0 = C + (size_t)r0 * D;
        float* C1 = C + (size_t)r1 * D;
#pragma unroll
        for (int nt = 0; nt < 8; nt++) {
            int col = ncol0 + nt * 8 + tig * 2;
            float b0 = sb[col], b1 = sb[col + 1];
            if (v0) {
                float2 o = make_float2(acc[nt][0] + b0, acc[nt][1] + b1);
                *(float2*)(C0 + col) = o;
            }
            if (v1) {
                float2 o = make_float2(acc[nt][2] + b0, acc[nt][3] + b1);
                *(float2*)(C1 + col) = o;
            }
        }
    }
}

// ---------------- 4) BN stats ----------------
__global__ void stats_kernel(const float* __restrict__ H,
                             float* __restrict__ sum, float* __restrict__ sq) {
    int col = threadIdx.x;
    int row0 = blockIdx.x * 128;
    float s = 0.f, q = 0.f;
#pragma unroll 4
    for (int r = 0; r < 128; r++) {
        int grow = row0 + r;
        if (grow < N_NODES) {
            float v = H[(size_t)grow * D + col];
            s += v;
            q = fmaf(v, v, q);
        }
    }
    atomicAdd(sum + col, s);
    atomicAdd(sq + col, q);
}

__global__ void finalize_kernel(const float* __restrict__ g,
                                const float* __restrict__ be,
                                const float* __restrict__ sum,
                                const float* __restrict__ sq) {
    int c = threadIdx.x;
    if (c >= D) return;
    float inv_n = 1.0f / (float)N_NODES;
    float mean = sum[c] * inv_n;
    float var = sq[c] * inv_n - mean * mean;
    float sc = g[c] * rsqrtf(var + BN_EPS);
    g_scale[c] = sc;
    g_shift[c] = be[c] - mean * sc;
}

// ---------------- 5) final apply: out = swish(bn(h2)) ----------------
__global__ void apply_kernel(const float* __restrict__ H, float* __restrict__ out) {
    int i = blockIdx.x * blockDim.x + threadIdx.x;
    int idx = i * 4;
    if (idx >= N_NODES * D) return;
    int col = idx & (D - 1);
    float4 v = *(const float4*)(H + idx);
    v.x = swishf(fmaf(v.x, g_scale[col + 0], g_shift[col + 0]));
    v.y = swishf(fmaf(v.y, g_scale[col + 1], g_shift[col + 1]));
    v.z = swishf(fmaf(v.z, g_scale[col + 2], g_shift[col + 2]));
    v.w = swishf(fmaf(v.w, g_scale[col + 3], g_shift[col + 3]));
    *(float4*)(out + idx) = v;
}

// ---------------- host ----------------
extern "C" void kernel_launch(void* const* d_in, const int* in_sizes, int n_in,
                              void* d_out, int out_size) {
    const float* x    = (const float*)d_in[0];
    const float* vals = (const float*)d_in[1];
    const float* W1   = (const float*)d_in[2];
    const float* b1   = (const float*)d_in[3];
    const float* g1   = (const float*)d_in[4];
    const float* be1  = (const float*)d_in[5];
    const float* W2   = (const float*)d_in[6];
    const float* b2   = (const float*)d_in[7];
    const float* g2   = (const float*)d_in[8];
    const float* be2  = (const float*)d_in[9];
    const float* eps  = (const float*)d_in[10];
    const int* rows   = (const int*)d_in[11];
    const int* cols   = (const int*)d_in[12];
    float* out = (float*)d_out;

    const int SMEM = 4 * TILE_B;  // 139264 bytes
    cudaFuncSetAttribute((const void*)gemm_mma_kernel<false>,
                         cudaFuncAttributeMaxDynamicSharedMemorySize, SMEM);
    cudaFuncSetAttribute((const void*)gemm_mma_kernel<true>,
                         cudaFuncAttributeMaxDynamicSharedMemorySize, SMEM);

    void *agg_p, *h1_p, *h2_p, *w1h_p, *w1l_p, *w2h_p, *w2l_p;
    void *s1_p, *q1_p, *s2_p, *q2_p;
    cudaGetSymbolAddress(&agg_p, g_agg);
    cudaGetSymbolAddress(&h1_p, g_h1);
    cudaGetSymbolAddress(&h2_p, g_h2);
    cudaGetSymbolAddress(&w1h_p, g_w1hi);
    cudaGetSymbolAddress(&w1l_p, g_w1lo);
    cudaGetSymbolAddress(&w2h_p, g_w2hi);
    cudaGetSymbolAddress(&w2l_p, g_w2lo);
    cudaGetSymbolAddress(&s1_p, g_sum1);
    cudaGetSymbolAddress(&q1_p, g_sq1);
    cudaGetSymbolAddress(&s2_p, g_sum2);
    cudaGetSymbolAddress(&q2_p, g_sq2);
    float* agg = (float*)agg_p;
    float* h1 = (float*)h1_p;
    float* h2 = (float*)h2_p;

    const int EW_BLOCKS = (N_NODES * D / 4 + 255) / 256;       // 6250
    const int PREP_BLOCKS = (N_NODES + 255) / 256;             // 196
    const int SCAT_BLOCKS = (N_EDGES + 255) / 256;             // 3125
    const int GATH_BLOCKS = (N_NODES + 7) / 8;                 // 6250
    const int TC_BLOCKS = (N_NODES + 127) / 128;               // 391
    const int STAT_BLOCKS = (N_NODES + 127) / 128;

    // 0) weight split + zero counters/stats
    prep_kernel<<<PREP_BLOCKS, 256>>>(W1, W2);
    // 1) bin edges by destination row
    scatter_kernel<<<SCAT_BLOCKS, 256>>>(vals, rows, cols);
    // 2) gather-accumulate (fused (1+eps)x init), plain stores
    gather_kernel<<<GATH_BLOCKS, 256>>>(x, eps);
    // 2b) overflow fixup (usually no-op)
    fixup_kernel<<<1, 256>>>(x, vals, rows, cols);
    // 3) h1 = agg @ W1 + b1
    gemm_mma_kernel<false><<<TC_BLOCKS, 512, SMEM>>>(
        agg, (const __nv_bfloat16*)w1h_p, (const __nv_bfloat16*)w1l_p, b1, h1);
    // 4) BN1 stats
    stats_kernel<<<STAT_BLOCKS, 128>>>(h1, (float*)s1_p, (float*)q1_p);
    finalize_kernel<<<1, 128>>>(g1, be1, (const float*)s1_p, (const float*)q1_p);
    // 5) h2 = swish(bn1(h1)) @ W2 + b2
    gemm_mma_kernel<true><<<TC_BLOCKS, 512, SMEM>>>(
        h1, (const __nv_bfloat16*)w2h_p, (const __nv_bfloat16*)w2l_p, b2, h2);
    // 6) BN2 stats
    stats_kernel<<<STAT_BLOCKS, 128>>>(h2, (float*)s2_p, (float*)q2_p);
    finalize_kernel<<<1, 128>>>(g2, be2, (const float*)s2_p, (const float*)q2_p);
    // 7) out = swish(bn2(h2))
    apply_kernel<<<EW_BLOCKS, 256>>>(h2, out);
}

// round 15
// speedup vs baseline: 1.3239x; 1.3239x over previous
#include <cuda_runtime.h>
#include <cuda_bf16.h>
#include <cstdint>

#define N_NODES 50000
#define N_EDGES 800000
#define D 128
#define BN_EPS 1e-5f
#define SLOTS 64
#define OVF_MAX 8192

// ---------------- scratch (no allocation allowed) ----------------
__device__ float g_agg[N_NODES * D];
__device__ float g_h1[N_NODES * D];
__device__ float g_h2[N_NODES * D];
__device__ float g_sum1[D], g_sq1[D], g_sum2[D], g_sq2[D];
__device__ float g_scale[D];
__device__ float g_shift[D];
__device__ int   g_cnt[N_NODES];
__device__ uint2 g_slots[N_NODES * SLOTS];   // {col, val bits}
__device__ int   g_ovf_cnt;
__device__ int   g_ovf[OVF_MAX];
// transposed + bf16-split weights: wt[n*D+k] = W[k*D+n]
__device__ __nv_bfloat16 g_w1hi[D * D];
__device__ __nv_bfloat16 g_w1lo[D * D];
__device__ __nv_bfloat16 g_w2hi[D * D];
__device__ __nv_bfloat16 g_w2lo[D * D];

__device__ __forceinline__ float swishf(float h) {
    return h / (1.0f + __expf(-h));
}

__device__ __forceinline__ uint32_t pack2(float a, float b) {
    __nv_bfloat162 t = __floats2bfloat162_rn(a, b);
    return *reinterpret_cast<uint32_t*>(&t);
}

__device__ __forceinline__ uint32_t smem_u32(const void* p) {
    uint32_t a;
    asm("{ .reg .u64 t; cvta.to.shared.u64 t, %1; cvt.u32.u64 %0, t; }"
        : "=r"(a) : "l"(p));
    return a;
}

// ---------------- 0) prep: weight split + zero counters/stats ----------------
__global__ void prep_kernel(const float* __restrict__ W1,
                            const float* __restrict__ W2) {
    int i = blockIdx.x * blockDim.x + threadIdx.x;   // 196*256 = 50176 threads
    if (i < D * D) {
        int n = i >> 7, k = i & (D - 1);
        float v1 = W1[k * D + n];
        float h1 = __bfloat162float(__float2bfloat16(v1));
        g_w1hi[i] = __float2bfloat16(v1);
        g_w1lo[i] = __float2bfloat16(v1 - h1);
        float v2 = W2[k * D + n];
        float h2 = __bfloat162float(__float2bfloat16(v2));
        g_w2hi[i] = __float2bfloat16(v2);
        g_w2lo[i] = __float2bfloat16(v2 - h2);
    }
    if (i < N_NODES) g_cnt[i] = 0;
    if (i < D) { g_sum1[i] = 0.f; g_sq1[i] = 0.f; g_sum2[i] = 0.f; g_sq2[i] = 0.f; }
    if (i == 0) g_ovf_cnt = 0;
}

// ---------------- 1) scatter edges into per-row slots ----------------
__global__ void scatter_kernel(const float* __restrict__ vals,
                               const int* __restrict__ rows,
                               const int* __restrict__ cols) {
    int e = blockIdx.x * blockDim.x + threadIdx.x;
    if (e >= N_EDGES) return;
    int r = __ldg(rows + e);
    int pos = atomicAdd(g_cnt + r, 1);
    if (pos < SLOTS) {
        uint2 cv;
        cv.x = (uint32_t)__ldg(cols + e);
        cv.y = __float_as_uint(__ldg(vals + e));
        g_slots[r * SLOTS + pos] = cv;
    } else {
        int o = atomicAdd(&g_ovf_cnt, 1);
        if (o < OVF_MAX) g_ovf[o] = e;
    }
}

// ---------------- 2) gather: agg[r] = (1+eps)x[r] + sum_slots val*x[col] ----------------
__global__ void gather_kernel(const float* __restrict__ x,
                              const float* __restrict__ eps) {
    int r = blockIdx.x * 8 + (threadIdx.x >> 5);
    int lane = threadIdx.x & 31;
    if (r >= N_NODES) return;
    int lane4 = lane * 4;

    float s = 1.0f + __ldg(eps);
    float4 acc = __ldg((const float4*)(x + (size_t)r * D + lane4));
    acc.x *= s; acc.y *= s; acc.z *= s; acc.w *= s;

    int n = g_cnt[r];
    if (n > SLOTS) n = SLOTS;
    uint2 cv0 = make_uint2(0, 0), cv1 = make_uint2(0, 0);
    if (lane < n) cv0 = g_slots[r * SLOTS + lane];
    if (lane + 32 < n) cv1 = g_slots[r * SLOTS + lane + 32];

    for (int j = 0; j < n; j += 4) {
        float4 m[4];
        float vv[4];
#pragma unroll
        for (int u = 0; u < 4; u++) {
            int jj = j + u;
            if (jj < n) {   // uniform branch
                uint32_t cx = __shfl_sync(0xffffffffu, (jj < 32) ? cv0.x : cv1.x, jj & 31);
                uint32_t cy = __shfl_sync(0xffffffffu, (jj < 32) ? cv0.y : cv1.y, jj & 31);
                vv[u] = __uint_as_float(cy);
                m[u] = __ldg((const float4*)(x + (size_t)cx * D + lane4));
            } else {
                vv[u] = 0.f;
                m[u] = make_float4(0.f, 0.f, 0.f, 0.f);
            }
        }
#pragma unroll
        for (int u = 0; u < 4; u++) {
            acc.x = fmaf(vv[u], m[u].x, acc.x);
            acc.y = fmaf(vv[u], m[u].y, acc.y);
            acc.z = fmaf(vv[u], m[u].z, acc.z);
            acc.w = fmaf(vv[u], m[u].w, acc.w);
        }
    }
    *(float4*)(g_agg + (size_t)r * D + lane4) = acc;
}

// ---------------- 2b) fixup: overflow edges (rare path, usually empty) ----------------
__global__ void fixup_kernel(const float* __restrict__ x,
                             const float* __restrict__ vals,
                             const int* __restrict__ rows,
                             const int* __restrict__ cols) {
    int n = g_ovf_cnt;
    if (n > OVF_MAX) n = OVF_MAX;
    int wid = threadIdx.x >> 5;
    int lane = threadIdx.x & 31;
    for (int i = wid; i < n; i += 8) {
        int e = g_ovf[i];
        int r = rows[e], c = cols[e];
        float v = vals[e];
        float4 m = __ldg((const float4*)(x + (size_t)c * D) + lane);
        m.x *= v; m.y *= v; m.z *= v; m.w *= v;
        float* dst = g_agg + (size_t)r * D + lane * 4;
        asm volatile("red.global.add.v4.f32 [%0], {%1,%2,%3,%4};"
                     :: "l"(dst), "f"(m.x), "f"(m.y), "f"(m.z), "f"(m.w)
                     : "memory");
    }
}

// ---------------- 3) mma.sync GEMM (R12 core) + fused stats accumulation ----------------
#define LDT (D + 8)             // 136 bf16 per row
#define TILE_B (128 * LDT * 2)  // 34816 bytes per tile

__device__ __forceinline__ void mma16816(float* c, const uint32_t* a,
                                         uint32_t b0, uint32_t b1) {
    asm volatile(
        "mma.sync.aligned.m16n8k16.row.col.f32.bf16.bf16.f32 "
        "{%0,%1,%2,%3}, {%4,%5,%6,%7}, {%8,%9}, {%0,%1,%2,%3};"
        : "+f"(c[0]), "+f"(c[1]), "+f"(c[2]), "+f"(c[3])
        : "r"(a[0]), "r"(a[1]), "r"(a[2]), "r"(a[3]), "r"(b0), "r"(b1));
}

__device__ __forceinline__ void ldsm4(uint32_t* r, uint32_t addr) {
    asm volatile("ldmatrix.sync.aligned.m8n8.x4.shared.b16 {%0,%1,%2,%3}, [%4];"
                 : "=r"(r[0]), "=r"(r[1]), "=r"(r[2]), "=r"(r[3])
                 : "r"(addr));
}

__device__ __forceinline__ float warp_red_group(float v) {
    // reduce over group (lane bits 2..4), keep per-tig lanes
    v += __shfl_xor_sync(0xffffffffu, v, 16);
    v += __shfl_xor_sync(0xffffffffu, v, 8);
    v += __shfl_xor_sync(0xffffffffu, v, 4);
    return v;
}

template <bool PRE>
__global__ __launch_bounds__(256, 1) void gemm_mma_kernel(
    const float* __restrict__ A,
    const __nv_bfloat16* __restrict__ Whi,
    const __nv_bfloat16* __restrict__ Wlo,
    const float* __restrict__ bias,
    float* __restrict__ C,
    float* __restrict__ sum, float* __restrict__ sq) {
    extern __shared__ char smem[];
    __nv_bfloat16* sAhi = (__nv_bfloat16*)(smem);
    __nv_bfloat16* sAlo = (__nv_bfloat16*)(smem + TILE_B);
    __nv_bfloat16* sWhi = (__nv_bfloat16*)(smem + 2 * TILE_B);
    __nv_bfloat16* sWlo = (__nv_bfloat16*)(smem + 3 * TILE_B);
    __shared__ float sb[D], ssc[D], ssh[D], sS[D], sQ[D];

    int tid = threadIdx.x;
    int wid = tid >> 5;
    int lane = tid & 31;
    int row0 = blockIdx.x * 128;

    if (tid < D) {
        sb[tid] = __ldg(bias + tid);
        sS[tid] = 0.f; sQ[tid] = 0.f;
        if (PRE) { ssc[tid] = g_scale[tid]; ssh[tid] = g_shift[tid]; }
    }
    __syncthreads();   // ssc/ssh read cross-thread below (R7 race fix)

    // ---- fill W tiles: thread t -> row t/2, half (t&1)*64 ----
    {
        int n = tid >> 1;
        int c0 = (tid & 1) * 64;
        const __nv_bfloat16* wh = Whi + n * D + c0;
        const __nv_bfloat16* wl = Wlo + n * D + c0;
        __nv_bfloat16* dh = sWhi + n * LDT + c0;
        __nv_bfloat16* dl = sWlo + n * LDT + c0;
#pragma unroll
        for (int j = 0; j < 64; j += 8) {
            *(uint4*)(dh + j) = *(const uint4*)(wh + j);
            *(uint4*)(dl + j) = *(const uint4*)(wl + j);
        }
    }

    // ---- fill A tiles (fp32 load, optional BN+swish, hi/lo split) ----
    {
        int r = tid >> 1;
        int c0 = (tid & 1) * 64;
        int grow = row0 + r;
        bool valid = grow < N_NODES;
        const float* Ar = A + (size_t)grow * D + c0;
        __nv_bfloat16* dh = sAhi + r * LDT + c0;
        __nv_bfloat16* dl = sAlo + r * LDT + c0;
#pragma unroll
        for (int j = 0; j < 64; j += 8) {
            float f[8];
            if (valid) {
                float4 v0 = *(const float4*)(Ar + j);
                float4 v1 = *(const float4*)(Ar + j + 4);
                f[0] = v0.x; f[1] = v0.y; f[2] = v0.z; f[3] = v0.w;
                f[4] = v1.x; f[5] = v1.y; f[6] = v1.z; f[7] = v1.w;
                if (PRE) {
#pragma unroll
                    for (int q = 0; q < 8; q++)
                        f[q] = swishf(fmaf(f[q], ssc[c0 + j + q], ssh[c0 + j + q]));
                }
            } else {
#pragma unroll
                for (int q = 0; q < 8; q++) f[q] = 0.f;
            }
            uint4 hi, lo;
            float hf[8];
#pragma unroll
            for (int q = 0; q < 8; q++)
                hf[q] = __bfloat162float(__float2bfloat16(f[q]));
            hi.x = pack2(f[0], f[1]); hi.y = pack2(f[2], f[3]);
            hi.z = pack2(f[4], f[5]); hi.w = pack2(f[6], f[7]);
            lo.x = pack2(f[0] - hf[0], f[1] - hf[1]);
            lo.y = pack2(f[2] - hf[2], f[3] - hf[3]);
            lo.z = pack2(f[4] - hf[4], f[5] - hf[5]);
            lo.w = pack2(f[6] - hf[6], f[7] - hf[7]);
            *(uint4*)(dh + j) = hi;
            *(uint4*)(dl + j) = lo;
        }
    }
    __syncthreads();

    // ---- MMA mainloop (ldmatrix fragment loads; R12 shape) ----
    int group = lane >> 2;
    int tig = lane & 3;
    int mrow = wid * 16;

    int aRow = mrow + ((lane >> 3) & 1) * 8 + (lane & 7);
    int aKadd = (lane >> 4) * 8;
    uint32_t aHiBase = smem_u32(sAhi) + (uint32_t)(aRow * LDT + aKadd) * 2u;
    uint32_t aLoBase = smem_u32(sAlo) + (uint32_t)(aRow * LDT + aKadd) * 2u;
    int bRowOff = ((lane >> 4) << 3) + (lane & 7);
    int bKadd = ((lane >> 3) & 1) * 8;
    uint32_t bHiBase = smem_u32(sWhi) + (uint32_t)(bRowOff * LDT + bKadd) * 2u;
    uint32_t bLoBase = smem_u32(sWlo) + (uint32_t)(bRowOff * LDT + bKadd) * 2u;

    float acc[16][4];
#pragma unroll
    for (int t = 0; t < 16; t++)
#pragma unroll
        for (int j = 0; j < 4; j++) acc[t][j] = 0.f;

#pragma unroll
    for (int kt = 0; kt < 8; kt++) {
        uint32_t kb = (uint32_t)(kt * 16) * 2u;
        uint32_t ahi[4], alo[4];
        ldsm4(ahi, aHiBase + kb);
        ldsm4(alo, aLoBase + kb);
#pragma unroll
        for (int p = 0; p < 8; p++) {
            uint32_t poff = (uint32_t)(p * 16 * LDT) * 2u;
            uint32_t bh[4], bl[4];
            ldsm4(bh, bHiBase + poff + kb);
            ldsm4(bl, bLoBase + poff + kb);
            // interleave the two accumulators: dependent MMAs at distance 2
            mma16816(acc[2 * p], ahi, bh[0], bh[1]);
            mma16816(acc[2 * p + 1], ahi, bh[2], bh[3]);
            mma16816(acc[2 * p], alo, bh[0], bh[1]);
            mma16816(acc[2 * p + 1], alo, bh[2], bh[3]);
            mma16816(acc[2 * p], ahi, bl[0], bl[1]);
            mma16816(acc[2 * p + 1], ahi, bl[2], bl[3]);
        }
    }

    // ---- epilogue: add bias, store fp32, fused per-column stats partials ----
    {
        int r0 = row0 + mrow + group;
        int r1 = r0 + 8;
        bool v0 = r0 < N_NODES;
        bool v1 = r1 < N_NODES;
        float* C0 = C + (size_t)r0 * D;
        float* C1 = C + (size_t)r1 * D;
#pragma unroll
        for (int nt = 0; nt < 16; nt++) {
            int col = nt * 8 + tig * 2;
            float b0 = sb[col], b1 = sb[col + 1];
            float o0 = acc[nt][0] + b0, o1 = acc[nt][1] + b1;
            float o2 = acc[nt][2] + b0, o3 = acc[nt][3] + b1;
            if (v0) *(float2*)(C0 + col) = make_float2(o0, o1);
            if (v1) *(float2*)(C1 + col) = make_float2(o2, o3);
            float s0 = (v0 ? o0 : 0.f) + (v1 ? o2 : 0.f);
            float q0 = (v0 ? o0 * o0 : 0.f) + (v1 ? o2 * o2 : 0.f);
            float s1 = (v0 ? o1 : 0.f) + (v1 ? o3 : 0.f);
            float q1 = (v0 ? o1 * o1 : 0.f) + (v1 ? o3 * o3 : 0.f);
            s0 = warp_red_group(s0); q0 = warp_red_group(q0);
            s1 = warp_red_group(s1); q1 = warp_red_group(q1);
            if (lane < 4) {   // lanes 0-3 hold warp totals for tig=lane
                int c2 = nt * 8 + lane * 2;
                atomicAdd(sS + c2, s0);
                atomicAdd(sQ + c2, q0);
                atomicAdd(sS + c2 + 1, s1);
                atomicAdd(sQ + c2 + 1, q1);
            }
        }
    }
    __syncthreads();
    if (tid < D) {
        atomicAdd(sum + tid, sS[tid]);
        atomicAdd(sq + tid, sQ[tid]);
    }
}

// ---------------- 4) BN finalize (separate tiny launch; NO fence in GEMM) ----------------
__global__ void finalize_kernel(const float* __restrict__ g,
                                const float* __restrict__ be,
                                const float* __restrict__ sum,
                                const float* __restrict__ sq) {
    int c = threadIdx.x;
    if (c >= D) return;
    float inv_n = 1.0f / (float)N_NODES;
    float mean = sum[c] * inv_n;
    float var = sq[c] * inv_n - mean * mean;
    float sc = g[c] * rsqrtf(var + BN_EPS);
    g_scale[c] = sc;
    g_shift[c] = be[c] - mean * sc;
}

// ---------------- 5) final apply: out = swish(bn(h2)) ----------------
__global__ void apply_kernel(const float* __restrict__ H, float* __restrict__ out) {
    int i = blockIdx.x * blockDim.x + threadIdx.x;
    int idx = i * 4;
    if (idx >= N_NODES * D) return;
    int col = idx & (D - 1);
    float4 v = *(const float4*)(H + idx);
    v.x = swishf(fmaf(v.x, g_scale[col + 0], g_shift[col + 0]));
    v.y = swishf(fmaf(v.y, g_scale[col + 1], g_shift[col + 1]));
    v.z = swishf(fmaf(v.z, g_scale[col + 2], g_shift[col + 2]));
    v.w = swishf(fmaf(v.w, g_scale[col + 3], g_shift[col + 3]));
    *(float4*)(out + idx) = v;
}

// ---------------- host ----------------
extern "C" void kernel_launch(void* const* d_in, const int* in_sizes, int n_in,
                              void* d_out, int out_size) {
    const float* x    = (const float*)d_in[0];
    const float* vals = (const float*)d_in[1];
    const float* W1   = (const float*)d_in[2];
    const float* b1   = (const float*)d_in[3];
    const float* g1   = (const float*)d_in[4];
    const float* be1  = (const float*)d_in[5];
    const float* W2   = (const float*)d_in[6];
    const float* b2   = (const float*)d_in[7];
    const float* g2   = (const float*)d_in[8];
    const float* be2  = (const float*)d_in[9];
    const float* eps  = (const float*)d_in[10];
    const int* rows   = (const int*)d_in[11];
    const int* cols   = (const int*)d_in[12];
    float* out = (float*)d_out;

    const int SMEM = 4 * TILE_B;  // 139264 bytes
    cudaFuncSetAttribute((const void*)gemm_mma_kernel<false>,
                         cudaFuncAttributeMaxDynamicSharedMemorySize, SMEM);
    cudaFuncSetAttribute((const void*)gemm_mma_kernel<true>,
                         cudaFuncAttributeMaxDynamicSharedMemorySize, SMEM);

    void *agg_p, *h1_p, *h2_p, *w1h_p, *w1l_p, *w2h_p, *w2l_p;
    void *s1_p, *q1_p, *s2_p, *q2_p;
    cudaGetSymbolAddress(&agg_p, g_agg);
    cudaGetSymbolAddress(&h1_p, g_h1);
    cudaGetSymbolAddress(&h2_p, g_h2);
    cudaGetSymbolAddress(&w1h_p, g_w1hi);
    cudaGetSymbolAddress(&w1l_p, g_w1lo);
    cudaGetSymbolAddress(&w2h_p, g_w2hi);
    cudaGetSymbolAddress(&w2l_p, g_w2lo);
    cudaGetSymbolAddress(&s1_p, g_sum1);
    cudaGetSymbolAddress(&q1_p, g_sq1);
    cudaGetSymbolAddress(&s2_p, g_sum2);
    cudaGetSymbolAddress(&q2_p, g_sq2);
    float* agg = (float*)agg_p;
    float* h1 = (float*)h1_p;
    float* h2 = (float*)h2_p;

    const int EW_BLOCKS = (N_NODES * D / 4 + 255) / 256;       // 6250
    const int PREP_BLOCKS = (N_NODES + 255) / 256;             // 196
    const int SCAT_BLOCKS = (N_EDGES + 255) / 256;             // 3125
    const int GATH_BLOCKS = (N_NODES + 7) / 8;                 // 6250
    const int TC_BLOCKS = (N_NODES + 127) / 128;               // 391

    // 0) weight split + zero counters/stats
    prep_kernel<<<PREP_BLOCKS, 256>>>(W1, W2);
    // 1) bin edges by destination row
    scatter_kernel<<<SCAT_BLOCKS, 256>>>(vals, rows, cols);
    // 2) gather-accumulate (fused (1+eps)x init), plain stores
    gather_kernel<<<GATH_BLOCKS, 256>>>(x, eps);
    // 2b) overflow fixup (usually no-op)
    fixup_kernel<<<1, 256>>>(x, vals, rows, cols);
    // 3) h1 = agg @ W1 + b1 ; stats1 accumulated in-epilogue
    gemm_mma_kernel<false><<<TC_BLOCKS, 256, SMEM>>>(
        agg, (const __nv_bfloat16*)w1h_p, (const __nv_bfloat16*)w1l_p, b1, h1,
        (float*)s1_p, (float*)q1_p);
    finalize_kernel<<<1, 128>>>(g1, be1, (const float*)s1_p, (const float*)q1_p);
    // 4) h2 = swish(bn1(h1)) @ W2 + b2 ; stats2 accumulated in-epilogue
    gemm_mma_kernel<true><<<TC_BLOCKS, 256, SMEM>>>(
        h1, (const __nv_bfloat16*)w2h_p, (const __nv_bfloat16*)w2l_p, b2, h2,
        (float*)s2_p, (float*)q2_p);
    finalize_kernel<<<1, 128>>>(g2, be2, (const float*)s2_p, (const float*)q2_p);
    // 5) out = swish(bn2(h2))
    apply_kernel<<<EW_BLOCKS, 256>>>(h2, out);
}